// round 1
// baseline (speedup 1.0000x reference)
#include <cuda_runtime.h>
#include <cuda_bf16.h>
#include <cstdint>

// ---- problem constants ----
#define BDIM 4
#define TDIM 4096
#define NTOK (BDIM * TDIM)      // 16384
#define DDIM 2048
#define HHEADS 4
#define EDIM 256
#define KDIM 2048               // H*2*E
#define TS 100000
#define VOCAB 50257
#define M0 20011
#define M1 30011
#define M2 40009

// Scratch (device globals: allocation-free rule)
__device__ float g_e[(size_t)NTOK * KDIM];   // gathered embeddings, [NTOK, 2048]
__device__ float g_v[(size_t)NTOK * DDIM];   // value projection, [NTOK, 2048]

// ---------------------------------------------------------------------------
// Kernel 1: hash + gather.  One block per token, 256 threads.
// e[t, 0:1024]  = tables2[h, i2(t), :]  h=0..3
// e[t, 1024:2048] = tables3[h, i3(t), :]
// ---------------------------------------------------------------------------
__global__ __launch_bounds__(256) void gather_kernel(
    const int* __restrict__ input_ids,
    const float* __restrict__ tables2,
    const float* __restrict__ tables3)
{
    int t = blockIdx.x;
    int tid = threadIdx.x;
    __shared__ int s_i2, s_i3;
    if (tid == 0) {
        int b = t / TDIM;
        int tt = t % TDIM;
        const int* row = input_ids + (size_t)b * TDIM;
        int id0 = row[tt];
        id0 = id0 < 0 ? 0 : (id0 > VOCAB - 1 ? VOCAB - 1 : id0);
        int s1 = 0, s2 = 0;
        if (tt >= 1) { s1 = row[tt - 1]; s1 = s1 < 0 ? 0 : (s1 > VOCAB - 1 ? VOCAB - 1 : s1); }
        if (tt >= 2) { s2 = row[tt - 2]; s2 = s2 < 0 ? 0 : (s2 > VOCAB - 1 ? VOCAB - 1 : s2); }
        int hash2 = (id0 * M0) ^ (s1 * M1);
        int hash3 = hash2 ^ (s2 * M2);
        int i2 = hash2 % TS; if (i2 < 0) i2 = 0;
        int i3 = hash3 % TS; if (i3 < 0) i3 = 0;
        s_i2 = i2; s_i3 = i3;
    }
    __syncthreads();
    int i2 = s_i2, i3 = s_i3;

    float* dst = g_e + (size_t)t * KDIM;
    // 512 float4 per token; each thread does 2.
    #pragma unroll
    for (int q = tid; q < 512; q += 256) {
        int seg = q >> 6;            // which of 8 segments of 256 floats
        int off = (q & 63) * 4;      // float offset within segment
        const float* src;
        if (seg < 4)
            src = tables2 + ((size_t)seg * TS + i2) * EDIM + off;
        else
            src = tables3 + ((size_t)(seg - 4) * TS + i3) * EDIM + off;
        *reinterpret_cast<float4*>(dst + (size_t)q * 4) =
            *reinterpret_cast<const float4*>(src);
    }
}

// ---------------------------------------------------------------------------
// Kernel 2: v = e @ Wv^T.
// A = g_e [M=16384, K=2048] row-major; B = Wv [N=2048, K=2048] row-major
// C[m][n] = sum_k A[m][k] * B[n][k]      (both K-contiguous, "NT" gemm)
// Classic 128x128x8 SGEMM, 256 threads, 8x8 microtile.
// ---------------------------------------------------------------------------
__global__ __launch_bounds__(256) void sgemm_nt_kernel(const float* __restrict__ Wv)
{
    __shared__ float As[8][128];
    __shared__ float Bs[8][128];

    const int tid = threadIdx.x;
    const int m0 = blockIdx.y * 128;
    const int n0 = blockIdx.x * 128;

    const float* Ag = g_e + (size_t)m0 * KDIM;
    const float* Bg = Wv + (size_t)n0 * KDIM;

    const int lr = tid >> 1;           // 0..127 tile row
    const int lk = (tid & 1) * 4;      // 0 or 4

    const int tm = (tid >> 4) * 8;     // output row offset
    const int tn = (tid & 15) * 8;     // output col offset

    float acc[8][8];
    #pragma unroll
    for (int i = 0; i < 8; i++)
        #pragma unroll
        for (int j = 0; j < 8; j++) acc[i][j] = 0.f;

    for (int k0 = 0; k0 < KDIM; k0 += 8) {
        float4 av = *reinterpret_cast<const float4*>(Ag + (size_t)lr * KDIM + k0 + lk);
        float4 bv = *reinterpret_cast<const float4*>(Bg + (size_t)lr * KDIM + k0 + lk);
        __syncthreads();
        As[lk + 0][lr] = av.x; As[lk + 1][lr] = av.y;
        As[lk + 2][lr] = av.z; As[lk + 3][lr] = av.w;
        Bs[lk + 0][lr] = bv.x; Bs[lk + 1][lr] = bv.y;
        Bs[lk + 2][lr] = bv.z; Bs[lk + 3][lr] = bv.w;
        __syncthreads();

        #pragma unroll
        for (int kk = 0; kk < 8; kk++) {
            float4 a0 = *reinterpret_cast<const float4*>(&As[kk][tm]);
            float4 a1 = *reinterpret_cast<const float4*>(&As[kk][tm + 4]);
            float4 b0 = *reinterpret_cast<const float4*>(&Bs[kk][tn]);
            float4 b1 = *reinterpret_cast<const float4*>(&Bs[kk][tn + 4]);
            float a[8] = {a0.x, a0.y, a0.z, a0.w, a1.x, a1.y, a1.z, a1.w};
            float b[8] = {b0.x, b0.y, b0.z, b0.w, b1.x, b1.y, b1.z, b1.w};
            #pragma unroll
            for (int i = 0; i < 8; i++)
                #pragma unroll
                for (int j = 0; j < 8; j++)
                    acc[i][j] = fmaf(a[i], b[j], acc[i][j]);
        }
    }

    float* Cg = g_v + (size_t)m0 * DDIM + n0;
    #pragma unroll
    for (int i = 0; i < 8; i++) {
        float4 c0 = make_float4(acc[i][0], acc[i][1], acc[i][2], acc[i][3]);
        float4 c1 = make_float4(acc[i][4], acc[i][5], acc[i][6], acc[i][7]);
        *reinterpret_cast<float4*>(Cg + (size_t)(tm + i) * DDIM + tn)     = c0;
        *reinterpret_cast<float4*>(Cg + (size_t)(tm + i) * DDIM + tn + 4) = c1;
    }
}

// ---------------------------------------------------------------------------
// Kernel 3: gating.  One block per token, 256 threads.
// gate = sigmoid( signed_sqrt( dot(rmsnorm(h)*wh, rmsnorm(v)*wv)/sqrt(D) ) )
// out = gate * v
// ---------------------------------------------------------------------------
__global__ __launch_bounds__(256) void gate_kernel(
    const float* __restrict__ hidden,
    const float* __restrict__ wh,
    const float* __restrict__ wv,
    float* __restrict__ out)
{
    int t = blockIdx.x;
    int tid = threadIdx.x;
    const float* h = hidden + (size_t)t * DDIM;
    const float* v = g_v + (size_t)t * DDIM;

    float4 v4[2];
    float shh = 0.f, svv = 0.f, shv = 0.f;
    #pragma unroll
    for (int r = 0; r < 2; r++) {
        int q = tid + r * 256;           // 0..511 float4 index
        float4 h4  = *reinterpret_cast<const float4*>(h + (size_t)q * 4);
        float4 x4  = *reinterpret_cast<const float4*>(v + (size_t)q * 4);
        float4 wh4 = *reinterpret_cast<const float4*>(wh + (size_t)q * 4);
        float4 wv4 = *reinterpret_cast<const float4*>(wv + (size_t)q * 4);
        v4[r] = x4;
        shh += h4.x * h4.x + h4.y * h4.y + h4.z * h4.z + h4.w * h4.w;
        svv += x4.x * x4.x + x4.y * x4.y + x4.z * x4.z + x4.w * x4.w;
        shv += (h4.x * wh4.x) * (x4.x * wv4.x)
             + (h4.y * wh4.y) * (x4.y * wv4.y)
             + (h4.z * wh4.z) * (x4.z * wv4.z)
             + (h4.w * wh4.w) * (x4.w * wv4.w);
    }

    // block reduce 3 sums
    #pragma unroll
    for (int o = 16; o > 0; o >>= 1) {
        shh += __shfl_down_sync(0xffffffffu, shh, o);
        svv += __shfl_down_sync(0xffffffffu, svv, o);
        shv += __shfl_down_sync(0xffffffffu, shv, o);
    }
    __shared__ float s0[8], s1[8], s2[8];
    int warp = tid >> 5, lane = tid & 31;
    if (lane == 0) { s0[warp] = shh; s1[warp] = svv; s2[warp] = shv; }
    __syncthreads();
    float thh = 0.f, tvv = 0.f, thv = 0.f;
    #pragma unroll
    for (int w = 0; w < 8; w++) { thh += s0[w]; tvv += s1[w]; thv += s2[w]; }

    const float eps = 1.1920928955078125e-7f;   // FLT_EPSILON, matches jnp eps
    float rh = rsqrtf(thh * (1.f / DDIM) + eps);
    float rv = rsqrtf(tvv * (1.f / DDIM) + eps);
    float gate = thv * rh * rv * (1.f / 45.254833995939045f);  // 1/sqrt(2048)
    float ga = fabsf(gate);
    ga = fmaxf(ga, 1e-6f);
    float gs = copysignf(sqrtf(ga), gate);
    float sig = 1.f / (1.f + expf(-gs));

    float* o = out + (size_t)t * DDIM;
    #pragma unroll
    for (int r = 0; r < 2; r++) {
        int q = tid + r * 256;
        float4 x = v4[r];
        x.x *= sig; x.y *= sig; x.z *= sig; x.w *= sig;
        *reinterpret_cast<float4*>(o + (size_t)q * 4) = x;
    }
}

// ---------------------------------------------------------------------------
extern "C" void kernel_launch(void* const* d_in, const int* in_sizes, int n_in,
                              void* d_out, int out_size)
{
    const float* hidden  = (const float*)d_in[0];
    const float* tables2 = (const float*)d_in[1];
    const float* tables3 = (const float*)d_in[2];
    const float* Wv      = (const float*)d_in[3];
    const float* wh      = (const float*)d_in[4];
    const float* wv      = (const float*)d_in[5];
    const int*   ids     = (const int*)d_in[6];
    float* out = (float*)d_out;

    gather_kernel<<<NTOK, 256>>>(ids, tables2, tables3);

    dim3 grid(DDIM / 128, NTOK / 128);   // (16, 128)
    sgemm_nt_kernel<<<grid, 256>>>(Wv);

    gate_kernel<<<NTOK, 256>>>(hidden, wh, wv, out);
}

// round 3
// speedup vs baseline: 2.4222x; 2.4222x over previous
#include <cuda_runtime.h>
#include <cuda_bf16.h>
#include <cstdint>

// ---- problem constants ----
#define BDIM 4
#define TDIM 4096
#define NTOK (BDIM * TDIM)      // 16384
#define DDIM 2048
#define KDIM 2048               // H*2*E
#define TS 100000
#define VOCAB 50257
#define M0 20011
#define M1 30011
#define M2 40009

// ---- device scratch (allocation-free rule) ----
__device__ __nv_bfloat16 g_e_hi[(size_t)NTOK * KDIM];
__device__ __nv_bfloat16 g_e_lo[(size_t)NTOK * KDIM];
__device__ __nv_bfloat16 g_w_hi[(size_t)DDIM * KDIM];
__device__ __nv_bfloat16 g_w_lo[(size_t)DDIM * KDIM];
__device__ float g_v[(size_t)NTOK * DDIM];

// ============================================================================
// Baseline-PTX helpers (NO tcgen05 — harness compiles for plain sm_103)
// ============================================================================
__device__ __forceinline__ uint32_t smem_to_u32(const void* p) {
    uint32_t a;
    asm("{ .reg .u64 t; cvta.to.shared.u64 t, %1; cvt.u32.u64 %0, t; }"
        : "=r"(a) : "l"(p));
    return a;
}

__device__ __forceinline__ void cp_async16(uint32_t smem_addr, const void* gptr) {
    asm volatile("cp.async.cg.shared.global [%0], [%1], 16;"
                 :: "r"(smem_addr), "l"(gptr) : "memory");
}
__device__ __forceinline__ void cp_commit() {
    asm volatile("cp.async.commit_group;" ::: "memory");
}
template <int N>
__device__ __forceinline__ void cp_wait_group() {
    asm volatile("cp.async.wait_group %0;" :: "n"(N) : "memory");
}

__device__ __forceinline__ void ldsm_x4(uint32_t* r, uint32_t addr) {
    asm volatile("ldmatrix.sync.aligned.m8n8.x4.shared.b16 {%0,%1,%2,%3}, [%4];"
                 : "=r"(r[0]), "=r"(r[1]), "=r"(r[2]), "=r"(r[3]) : "r"(addr));
}

__device__ __forceinline__ void mma_bf16(float* d, const uint32_t* a,
                                         uint32_t b0, uint32_t b1) {
    asm volatile(
        "mma.sync.aligned.m16n8k16.row.col.f32.bf16.bf16.f32 "
        "{%0,%1,%2,%3}, {%4,%5,%6,%7}, {%8,%9}, {%0,%1,%2,%3};"
        : "+f"(d[0]), "+f"(d[1]), "+f"(d[2]), "+f"(d[3])
        : "r"(a[0]), "r"(a[1]), "r"(a[2]), "r"(a[3]), "r"(b0), "r"(b1));
}

// ============================================================================
// Kernel 0: split Wv fp32 -> (hi, lo) bf16 planes
// ============================================================================
__global__ __launch_bounds__(256) void wconv_kernel(const float* __restrict__ Wv)
{
    size_t base = ((size_t)blockIdx.x * 256 + threadIdx.x) * 8;
    float4 x0 = *reinterpret_cast<const float4*>(Wv + base);
    float4 x1 = *reinterpret_cast<const float4*>(Wv + base + 4);
    float xs[8] = {x0.x, x0.y, x0.z, x0.w, x1.x, x1.y, x1.z, x1.w};
    __nv_bfloat16 hi[8], lo[8];
    #pragma unroll
    for (int j = 0; j < 8; j++) {
        hi[j] = __float2bfloat16_rn(xs[j]);
        lo[j] = __float2bfloat16_rn(xs[j] - __bfloat162float(hi[j]));
    }
    *reinterpret_cast<uint4*>(g_w_hi + base) = *reinterpret_cast<uint4*>(hi);
    *reinterpret_cast<uint4*>(g_w_lo + base) = *reinterpret_cast<uint4*>(lo);
}

// ============================================================================
// Kernel 1: hash + gather + split -> e_hi/e_lo bf16 planes
// ============================================================================
__global__ __launch_bounds__(256) void gather_kernel(
    const int* __restrict__ input_ids,
    const float* __restrict__ tables2,
    const float* __restrict__ tables3)
{
    int t = blockIdx.x;
    int tid = threadIdx.x;
    __shared__ int s_i2, s_i3;
    if (tid == 0) {
        int b = t / TDIM;
        int tt = t % TDIM;
        const int* row = input_ids + (size_t)b * TDIM;
        int id0 = row[tt];
        id0 = id0 < 0 ? 0 : (id0 > VOCAB - 1 ? VOCAB - 1 : id0);
        int s1 = 0, s2 = 0;
        if (tt >= 1) { s1 = row[tt - 1]; s1 = s1 < 0 ? 0 : (s1 > VOCAB - 1 ? VOCAB - 1 : s1); }
        if (tt >= 2) { s2 = row[tt - 2]; s2 = s2 < 0 ? 0 : (s2 > VOCAB - 1 ? VOCAB - 1 : s2); }
        int hash2 = (id0 * M0) ^ (s1 * M1);
        int hash3 = hash2 ^ (s2 * M2);
        int i2 = hash2 % TS; if (i2 < 0) i2 = 0;
        int i3 = hash3 % TS; if (i3 < 0) i3 = 0;
        s_i2 = i2; s_i3 = i3;
    }
    __syncthreads();
    int i2 = s_i2, i3 = s_i3;

    int f0 = tid * 8;
    int seg = f0 >> 8;
    int off = f0 & 255;
    const float* src = (seg < 4)
        ? tables2 + ((size_t)seg * TS + i2) * 256 + off
        : tables3 + ((size_t)(seg - 4) * TS + i3) * 256 + off;

    float4 x0 = *reinterpret_cast<const float4*>(src);
    float4 x1 = *reinterpret_cast<const float4*>(src + 4);
    float xs[8] = {x0.x, x0.y, x0.z, x0.w, x1.x, x1.y, x1.z, x1.w};
    __nv_bfloat16 hi[8], lo[8];
    #pragma unroll
    for (int j = 0; j < 8; j++) {
        hi[j] = __float2bfloat16_rn(xs[j]);
        lo[j] = __float2bfloat16_rn(xs[j] - __bfloat162float(hi[j]));
    }
    size_t dst = (size_t)t * KDIM + f0;
    *reinterpret_cast<uint4*>(g_e_hi + dst) = *reinterpret_cast<uint4*>(hi);
    *reinterpret_cast<uint4*>(g_e_lo + dst) = *reinterpret_cast<uint4*>(lo);
}

// ============================================================================
// Kernel 2: bf16 split GEMM via mma.sync (HMMA), fp32 accum in registers.
//   C[m][n] = sum_k e[m][k] * Wv[n][k]   both K-contiguous (NT)
//   CTA tile 128x128, k-chunk 32, 3-stage cp.async pipeline.
//   3 terms: hi*hi + hi*lo + lo*hi.
// Smem stage layout (32KB):
//   A region @0:      256 rows (128 hi + 128 lo) x 64B (32 bf16)
//   B region @16384:  256 rows x 64B
//   swizzle: chunk(16B unit 0..3) ^= (row>>1)&3
// ============================================================================
#define NK (KDIM / 32)            // 64 chunks
#define STAGES 3
#define STAGE_BYTES 32768
#define GEMM_SMEM (STAGES * STAGE_BYTES)   // 98304

__global__ __launch_bounds__(256, 1) void gemm_kernel()
{
    extern __shared__ char smem[];
    const uint32_t sbase = smem_to_u32(smem);
    const int tid = threadIdx.x;
    const int lane = tid & 31;
    const int wid = tid >> 5;
    const int warpM = wid & 1;        // 2 warps in M
    const int warpN = wid >> 1;       // 4 warps in N
    const int m0 = blockIdx.y * 128;
    const int n0 = blockIdx.x * 128;

    // ---- per-thread cp.async mapping (8 x 16B per stage) ----
    const __nv_bfloat16* src[8];
    uint32_t dstoff[8];
    #pragma unroll
    for (int i = 0; i < 8; i++) {
        int g = tid + i * 256;               // 0..2047
        int isB = g >= 1024;
        int gl = g & 1023;
        int row = gl >> 2;                   // 0..255 (plane-major)
        int ch = gl & 3;
        int plane = row >> 7;
        int r = row & 127;
        const __nv_bfloat16* base = isB ? (plane ? g_w_lo : g_w_hi)
                                        : (plane ? g_e_lo : g_e_hi);
        int rowg = (isB ? n0 : m0) + r;
        src[i] = base + (size_t)rowg * KDIM + ch * 8;
        dstoff[i] = (isB ? 16384u : 0u) + (uint32_t)row * 64u
                  + (uint32_t)((ch ^ ((row >> 1) & 3)) << 4);
    }

    // ---- ldmatrix address components ----
    const int l15 = lane & 15;
    const int lhi = lane >> 4;
    const int s = (l15 >> 1) & 3;
    const uint32_t aRowBase = (uint32_t)(warpM * 64 + l15) * 64u;
    const uint32_t bRowBase = (uint32_t)(warpN * 32 + l15) * 64u;
    const uint32_t chj[2] = { (uint32_t)((lhi ^ s) << 4),
                              (uint32_t)(((2 + lhi) ^ s) << 4) };

    float acc[4][4][4];
    #pragma unroll
    for (int mf = 0; mf < 4; mf++)
        #pragma unroll
        for (int nf = 0; nf < 4; nf++)
            #pragma unroll
            for (int q = 0; q < 4; q++) acc[mf][nf][q] = 0.f;

    // ---- prologue: preload stages 0, 1 ----
    #pragma unroll
    for (int st = 0; st < 2; st++) {
        uint32_t sb = sbase + st * STAGE_BYTES;
        #pragma unroll
        for (int i = 0; i < 8; i++)
            cp_async16(sb + dstoff[i], src[i] + st * 32);
        cp_commit();
    }

    int buf = 0;
    for (int kt = 0; kt < NK; kt++) {
        if (kt + 1 < NK) cp_wait_group<1>(); else cp_wait_group<0>();
        __syncthreads();

        if (kt + 2 < NK) {
            int nb = buf + 2; if (nb >= STAGES) nb -= STAGES;
            uint32_t sb = sbase + nb * STAGE_BYTES;
            #pragma unroll
            for (int i = 0; i < 8; i++)
                cp_async16(sb + dstoff[i], src[i] + (kt + 2) * 32);
            cp_commit();
        }

        const uint32_t sb = sbase + buf * STAGE_BYTES;
        #pragma unroll
        for (int j = 0; j < 2; j++) {
            const uint32_t co = chj[j];
            uint32_t a[2][4][4];
            uint32_t b[2][2][4];
            #pragma unroll
            for (int p = 0; p < 2; p++)
                #pragma unroll
                for (int mf = 0; mf < 4; mf++)
                    ldsm_x4(a[p][mf], sb + aRowBase + (uint32_t)(p * 8192 + mf * 1024) + co);
            #pragma unroll
            for (int p = 0; p < 2; p++)
                #pragma unroll
                for (int nh = 0; nh < 2; nh++)
                    ldsm_x4(b[p][nh], sb + 16384u + bRowBase + (uint32_t)(p * 8192 + nh * 1024) + co);

            #pragma unroll
            for (int mf = 0; mf < 4; mf++)
                #pragma unroll
                for (int nf = 0; nf < 4; nf++) {
                    const int nh = nf >> 1, su = nf & 1;
                    // hi*hi
                    mma_bf16(acc[mf][nf], a[0][mf], b[0][nh][su], b[0][nh][su + 2]);
                    // hi*lo
                    mma_bf16(acc[mf][nf], a[0][mf], b[1][nh][su], b[1][nh][su + 2]);
                    // lo*hi
                    mma_bf16(acc[mf][nf], a[1][mf], b[0][nh][su], b[0][nh][su + 2]);
                }
        }
        buf++; if (buf >= STAGES) buf = 0;
    }

    // ---- epilogue: write fp32 result ----
    const int grp = lane >> 2;
    const int q2 = (lane & 3) * 2;
    #pragma unroll
    for (int mf = 0; mf < 4; mf++) {
        #pragma unroll
        for (int nf = 0; nf < 4; nf++) {
            int r = m0 + warpM * 64 + mf * 16 + grp;
            int c = n0 + warpN * 32 + nf * 8 + q2;
            float2 v0 = make_float2(acc[mf][nf][0], acc[mf][nf][1]);
            float2 v1 = make_float2(acc[mf][nf][2], acc[mf][nf][3]);
            *reinterpret_cast<float2*>(g_v + (size_t)r * DDIM + c) = v0;
            *reinterpret_cast<float2*>(g_v + (size_t)(r + 8) * DDIM + c) = v1;
        }
    }
}

// ============================================================================
// Kernel 3: gating
// ============================================================================
__global__ __launch_bounds__(256) void gate_kernel(
    const float* __restrict__ hidden,
    const float* __restrict__ wh,
    const float* __restrict__ wv,
    float* __restrict__ out)
{
    int t = blockIdx.x;
    int tid = threadIdx.x;
    const float* h = hidden + (size_t)t * DDIM;
    const float* v = g_v + (size_t)t * DDIM;

    float4 v4[2];
    float shh = 0.f, svv = 0.f, shv = 0.f;
    #pragma unroll
    for (int r = 0; r < 2; r++) {
        int q = tid + r * 256;
        float4 h4  = *reinterpret_cast<const float4*>(h + (size_t)q * 4);
        float4 x4  = *reinterpret_cast<const float4*>(v + (size_t)q * 4);
        float4 wh4 = *reinterpret_cast<const float4*>(wh + (size_t)q * 4);
        float4 wv4 = *reinterpret_cast<const float4*>(wv + (size_t)q * 4);
        v4[r] = x4;
        shh += h4.x * h4.x + h4.y * h4.y + h4.z * h4.z + h4.w * h4.w;
        svv += x4.x * x4.x + x4.y * x4.y + x4.z * x4.z + x4.w * x4.w;
        shv += (h4.x * wh4.x) * (x4.x * wv4.x)
             + (h4.y * wh4.y) * (x4.y * wv4.y)
             + (h4.z * wh4.z) * (x4.z * wv4.z)
             + (h4.w * wh4.w) * (x4.w * wv4.w);
    }

    #pragma unroll
    for (int o = 16; o > 0; o >>= 1) {
        shh += __shfl_down_sync(0xffffffffu, shh, o);
        svv += __shfl_down_sync(0xffffffffu, svv, o);
        shv += __shfl_down_sync(0xffffffffu, shv, o);
    }
    __shared__ float s0[8], s1[8], s2[8];
    int warp = tid >> 5, lane = tid & 31;
    if (lane == 0) { s0[warp] = shh; s1[warp] = svv; s2[warp] = shv; }
    __syncthreads();
    float thh = 0.f, tvv = 0.f, thv = 0.f;
    #pragma unroll
    for (int w = 0; w < 8; w++) { thh += s0[w]; tvv += s1[w]; thv += s2[w]; }

    const float eps = 1.1920928955078125e-7f;
    float rh = rsqrtf(thh * (1.f / DDIM) + eps);
    float rv = rsqrtf(tvv * (1.f / DDIM) + eps);
    float gate = thv * rh * rv * (1.f / 45.254833995939045f);
    float ga = fabsf(gate);
    ga = fmaxf(ga, 1e-6f);
    float gs = copysignf(sqrtf(ga), gate);
    float sig = 1.f / (1.f + expf(-gs));

    float* o = out + (size_t)t * DDIM;
    #pragma unroll
    for (int r = 0; r < 2; r++) {
        int q = tid + r * 256;
        float4 x = v4[r];
        x.x *= sig; x.y *= sig; x.z *= sig; x.w *= sig;
        *reinterpret_cast<float4*>(o + (size_t)q * 4) = x;
    }
}

// ---------------------------------------------------------------------------
extern "C" void kernel_launch(void* const* d_in, const int* in_sizes, int n_in,
                              void* d_out, int out_size)
{
    const float* hidden  = (const float*)d_in[0];
    const float* tables2 = (const float*)d_in[1];
    const float* tables3 = (const float*)d_in[2];
    const float* Wv      = (const float*)d_in[3];
    const float* wh      = (const float*)d_in[4];
    const float* wv      = (const float*)d_in[5];
    const int*   ids     = (const int*)d_in[6];
    float* out = (float*)d_out;

    static bool attr_set = false;
    if (!attr_set) {
        cudaFuncSetAttribute(gemm_kernel,
                             cudaFuncAttributeMaxDynamicSharedMemorySize, GEMM_SMEM);
        attr_set = true;
    }

    wconv_kernel<<<(DDIM * KDIM) / (256 * 8), 256>>>(Wv);
    gather_kernel<<<NTOK, 256>>>(ids, tables2, tables3);

    dim3 grid(DDIM / 128, NTOK / 128);   // x = N tiles (share A within a wave)
    gemm_kernel<<<grid, 256, GEMM_SMEM>>>();

    gate_kernel<<<NTOK, 256>>>(hidden, wh, wv, out);
}